// round 1
// baseline (speedup 1.0000x reference)
#include <cuda_runtime.h>
#include <math.h>

#define BATCH 2
#define SEQ   2048
#define DM    1024
#define NH    16
#define HD    64
#define HALF  256
#define PAD   68

__device__ float g_qkv[BATCH * SEQ * 3 * DM];   // [B,N,3,H,Dh] flattened
__device__ float g_attn[BATCH * SEQ * DM];      // [B,N,C] attention output

// ---------------------------------------------------------------------------
// SGEMM: C[M,N] = A[M,K] @ B[K,N] (+ bias). M%128==0, N%128==0, K%16==0.
// 256 threads, 128x128 block tile, BK=16, 8x8 per-thread register tile.
// ---------------------------------------------------------------------------
__global__ void __launch_bounds__(256) sgemm_kernel(
    const float* __restrict__ A, const float* __restrict__ B,
    float* __restrict__ C, const float* __restrict__ bias,
    int M, int N, int K)
{
    __shared__ float As[16][128];   // transposed: As[k][m]
    __shared__ float Bs[16][128];

    const int tid = threadIdx.x;
    const int tx = tid & 15;        // 0..15 -> cols
    const int ty = tid >> 4;        // 0..15 -> rows
    const int m0 = blockIdx.y * 128;
    const int n0 = blockIdx.x * 128;

    // loader indices
    const int ar = tid >> 2;          // 0..63 (rows ar, ar+64)
    const int ac = (tid & 3) * 4;     // 0..12
    const int br = tid >> 5;          // 0..7  (rows br, br+8)
    const int bc = (tid & 31) * 4;    // 0..124

    float acc[8][8];
    #pragma unroll
    for (int i = 0; i < 8; i++)
        #pragma unroll
        for (int j = 0; j < 8; j++) acc[i][j] = 0.f;

    const float* Ap = A + (size_t)m0 * K;
    const float* Bp = B + n0;

    for (int k0 = 0; k0 < K; k0 += 16) {
        float4 a0 = *(const float4*)(Ap + (size_t)ar * K + k0 + ac);
        float4 a1 = *(const float4*)(Ap + (size_t)(ar + 64) * K + k0 + ac);
        As[ac + 0][ar] = a0.x; As[ac + 1][ar] = a0.y;
        As[ac + 2][ar] = a0.z; As[ac + 3][ar] = a0.w;
        As[ac + 0][ar + 64] = a1.x; As[ac + 1][ar + 64] = a1.y;
        As[ac + 2][ar + 64] = a1.z; As[ac + 3][ar + 64] = a1.w;

        float4 b0 = *(const float4*)(Bp + (size_t)(k0 + br) * N + bc);
        float4 b1 = *(const float4*)(Bp + (size_t)(k0 + br + 8) * N + bc);
        *(float4*)&Bs[br][bc]     = b0;
        *(float4*)&Bs[br + 8][bc] = b1;
        __syncthreads();

        #pragma unroll
        for (int k = 0; k < 16; k++) {
            float a[8], b[8];
            *(float4*)&a[0] = *(const float4*)&As[k][ty * 8];
            *(float4*)&a[4] = *(const float4*)&As[k][ty * 8 + 4];
            *(float4*)&b[0] = *(const float4*)&Bs[k][tx * 8];
            *(float4*)&b[4] = *(const float4*)&Bs[k][tx * 8 + 4];
            #pragma unroll
            for (int i = 0; i < 8; i++)
                #pragma unroll
                for (int j = 0; j < 8; j++)
                    acc[i][j] += a[i] * b[j];
        }
        __syncthreads();
    }

    #pragma unroll
    for (int i = 0; i < 8; i++) {
        const int row = m0 + ty * 8 + i;
        #pragma unroll
        for (int j4 = 0; j4 < 8; j4 += 4) {
            const int col = n0 + tx * 8 + j4;
            float4 v = make_float4(acc[i][j4], acc[i][j4 + 1],
                                   acc[i][j4 + 2], acc[i][j4 + 3]);
            if (bias) {
                v.x += bias[col];     v.y += bias[col + 1];
                v.z += bias[col + 2]; v.w += bias[col + 3];
            }
            *(float4*)(C + (size_t)row * N + col) = v;
        }
    }
}

// ---------------------------------------------------------------------------
// Banded flash attention. One CTA = 64 queries of one (b,h). 128 threads.
// Thread (tx=tid%8, ty=tid/8) owns rows ty*4+[0,4), cols tx*8+[0,8).
// ---------------------------------------------------------------------------
__global__ void __launch_bounds__(128) attn_kernel(
    const float* __restrict__ qkv, float* __restrict__ out)
{
    extern __shared__ float smem[];
    float* Qs = smem;                 // [64][PAD], pre-scaled
    float* Kt = Qs + 64 * PAD;        // [64][PAD], d-major: Kt[d][j]
    float* Vs = Kt + 64 * PAD;        // [64][PAD], Vs[j][d]
    float* Ss = Vs + 64 * PAD;        // [64][PAD], probabilities

    const int tid = threadIdx.x;
    const int tx = tid & 7;           // 0..7
    const int ty = tid >> 3;          // 0..15
    const int n0 = blockIdx.x * 64;
    const int h  = blockIdx.y;
    const int b  = blockIdx.z;
    const float scale = 0.125f;       // 1/sqrt(64)

    const float* qbase = qkv + (size_t)b * SEQ * 3 * DM + h * HD;

    // load Q tile, pre-scaled
    for (int idx = tid; idx < 64 * 16; idx += 128) {
        const int r  = idx >> 4;
        const int c4 = (idx & 15) * 4;
        float4 v = *(const float4*)(qbase + (size_t)(n0 + r) * 3 * DM + c4);
        v.x *= scale; v.y *= scale; v.z *= scale; v.w *= scale;
        *(float4*)&Qs[r * PAD + c4] = v;
    }

    float m[4], l[4], o[4][8];
    #pragma unroll
    for (int r = 0; r < 4; r++) {
        m[r] = -INFINITY; l[r] = 0.f;
        #pragma unroll
        for (int c = 0; c < 8; c++) o[r][c] = 0.f;
    }

    const int jlo = max(0, n0 - HALF);
    const int jhi = min(SEQ, n0 + 64 + HALF);

    for (int j0 = jlo; j0 < jhi; j0 += 64) {
        __syncthreads();   // previous PV done before overwriting Kt/Vs

        // load K (transposed) and V tiles
        for (int idx = tid; idx < 64 * 16; idx += 128) {
            const int r  = idx >> 4;
            const int c4 = (idx & 15) * 4;
            const float* rowp = qbase + (size_t)(j0 + r) * 3 * DM;
            float4 kv = *(const float4*)(rowp + DM + c4);
            Kt[(c4 + 0) * PAD + r] = kv.x;
            Kt[(c4 + 1) * PAD + r] = kv.y;
            Kt[(c4 + 2) * PAD + r] = kv.z;
            Kt[(c4 + 3) * PAD + r] = kv.w;
            float4 vv = *(const float4*)(rowp + 2 * DM + c4);
            *(float4*)&Vs[r * PAD + c4] = vv;
        }
        __syncthreads();

        // scores: S = (Q*scale) @ K^T
        float s[4][8];
        #pragma unroll
        for (int r = 0; r < 4; r++)
            #pragma unroll
            for (int c = 0; c < 8; c++) s[r][c] = 0.f;

        for (int d = 0; d < 64; d += 4) {
            float q[4][4];
            #pragma unroll
            for (int r = 0; r < 4; r++)
                *(float4*)q[r] = *(const float4*)&Qs[(ty * 4 + r) * PAD + d];
            #pragma unroll
            for (int dd = 0; dd < 4; dd++) {
                float kk[8];
                *(float4*)&kk[0] = *(const float4*)&Kt[(d + dd) * PAD + tx * 8];
                *(float4*)&kk[4] = *(const float4*)&Kt[(d + dd) * PAD + tx * 8 + 4];
                #pragma unroll
                for (int r = 0; r < 4; r++)
                    #pragma unroll
                    for (int c = 0; c < 8; c++)
                        s[r][c] += q[r][dd] * kk[c];
            }
        }

        // masked online softmax
        #pragma unroll
        for (int r = 0; r < 4; r++) {
            const int i = n0 + ty * 4 + r;
            float mx = -INFINITY;
            #pragma unroll
            for (int c = 0; c < 8; c++) {
                const int j = j0 + tx * 8 + c;
                const bool ok = (j >= i - HALF) && (j <= i + HALF);
                s[r][c] = ok ? s[r][c] : -INFINITY;
                mx = fmaxf(mx, s[r][c]);
            }
            mx = fmaxf(mx, __shfl_xor_sync(0xffffffffu, mx, 1));
            mx = fmaxf(mx, __shfl_xor_sync(0xffffffffu, mx, 2));
            mx = fmaxf(mx, __shfl_xor_sync(0xffffffffu, mx, 4));
            const float newm = fmaxf(m[r], mx);
            const float corr = __expf(m[r] - newm);
            float sum = 0.f;
            #pragma unroll
            for (int c = 0; c < 8; c++) {
                const float p = (s[r][c] == -INFINITY) ? 0.f
                                                       : __expf(s[r][c] - newm);
                Ss[(ty * 4 + r) * PAD + tx * 8 + c] = p;
                sum += p;
            }
            sum += __shfl_xor_sync(0xffffffffu, sum, 1);
            sum += __shfl_xor_sync(0xffffffffu, sum, 2);
            sum += __shfl_xor_sync(0xffffffffu, sum, 4);
            l[r] = l[r] * corr + sum;
            m[r] = newm;
            #pragma unroll
            for (int c = 0; c < 8; c++) o[r][c] *= corr;
        }
        __syncthreads();   // Ss complete before PV reads cross-thread rows

        // O += P @ V
        for (int j = 0; j < 64; j += 4) {
            float p[4][4];
            #pragma unroll
            for (int r = 0; r < 4; r++)
                *(float4*)p[r] = *(const float4*)&Ss[(ty * 4 + r) * PAD + j];
            #pragma unroll
            for (int jj = 0; jj < 4; jj++) {
                float v8[8];
                *(float4*)&v8[0] = *(const float4*)&Vs[(j + jj) * PAD + tx * 8];
                *(float4*)&v8[4] = *(const float4*)&Vs[(j + jj) * PAD + tx * 8 + 4];
                #pragma unroll
                for (int r = 0; r < 4; r++)
                    #pragma unroll
                    for (int c = 0; c < 8; c++)
                        o[r][c] += p[r][jj] * v8[c];
            }
        }
    }

    // normalize + write to [B,N,C] scratch (head-interleaved layout)
    #pragma unroll
    for (int r = 0; r < 4; r++) {
        const int i = n0 + ty * 4 + r;
        const float inv = 1.f / l[r];
        float* op = out + ((size_t)(b * SEQ + i)) * DM + h * HD + tx * 8;
        float4 v0 = make_float4(o[r][0] * inv, o[r][1] * inv,
                                o[r][2] * inv, o[r][3] * inv);
        float4 v1 = make_float4(o[r][4] * inv, o[r][5] * inv,
                                o[r][6] * inv, o[r][7] * inv);
        *(float4*)op = v0;
        *(float4*)(op + 4) = v1;
    }
}

// ---------------------------------------------------------------------------
extern "C" void kernel_launch(void* const* d_in, const int* in_sizes, int n_in,
                              void* d_out, int out_size)
{
    const float* x     = (const float*)d_in[0];  // [2,2048,1024]
    const float* Wqkv  = (const float*)d_in[1];  // [1024,3072]
    const float* Wproj = (const float*)d_in[2];  // [1024,1024]
    const float* bproj = (const float*)d_in[3];  // [1024]
    float* out = (float*)d_out;                  // [2,2048,1024]

    float *qkv, *attn;
    cudaGetSymbolAddress((void**)&qkv, g_qkv);
    cudaGetSymbolAddress((void**)&attn, g_attn);

    const int M = BATCH * SEQ;                   // 4096
    const size_t smem_bytes = 4 * 64 * PAD * sizeof(float);  // 69632
    cudaFuncSetAttribute(attn_kernel,
                         cudaFuncAttributeMaxDynamicSharedMemorySize,
                         (int)smem_bytes);

    // 1) QKV projection
    {
        dim3 grid(3 * DM / 128, M / 128);
        sgemm_kernel<<<grid, 256>>>(x, Wqkv, qkv, nullptr, M, 3 * DM, DM);
    }
    // 2) banded attention
    {
        dim3 grid(SEQ / 64, NH, BATCH);
        attn_kernel<<<grid, 128, smem_bytes>>>(qkv, attn);
    }
    // 3) output projection + bias
    {
        dim3 grid(DM / 128, M / 128);
        sgemm_kernel<<<grid, 256>>>(attn, Wproj, out, bproj, M, DM, DM);
    }
}

// round 3
// speedup vs baseline: 1.8458x; 1.8458x over previous
#include <cuda_runtime.h>
#include <math.h>
#include <stdint.h>

#define BATCH 2
#define SEQ   2048
#define DM    1024
#define NH    16
#define HD    64
#define HALF  256
#define PAD   68

// ---------------- scratch (no allocations allowed) ----------------
__device__ float g_qkv[BATCH * SEQ * 3 * DM];   // [B,N,3,H,Dh]
__device__ float g_attn[BATCH * SEQ * DM];      // [B,N,C] (tf32-rounded)
__device__ float g_xr[BATCH * SEQ * DM];        // x rounded to tf32
__device__ float g_wqkvT[3 * DM * DM];          // [3C, C] transposed+rounded
__device__ float g_wprojT[DM * DM];             // [C, C]  transposed+rounded

// ---------------- helpers ----------------
__device__ __forceinline__ float tf32r(float x) {
    uint32_t u; asm("cvt.rna.tf32.f32 %0, %1;" : "=r"(u) : "f"(x));
    return __uint_as_float(u);
}
__device__ __forceinline__ uint32_t smem_u32(const void* p) {
    uint32_t a;
    asm("{ .reg .u64 t; cvta.to.shared.u64 t, %1; cvt.u32.u64 %0, t; }"
        : "=r"(a) : "l"(p));
    return a;
}
__device__ __forceinline__ void cpa16(uint32_t dst, const void* src) {
    asm volatile("cp.async.cg.shared.global [%0], [%1], 16;"
                 :: "r"(dst), "l"(src));
}
#define CP_COMMIT() asm volatile("cp.async.commit_group;" ::: "memory")
#define CP_WAIT(n)  asm volatile("cp.async.wait_group %0;" :: "n"(n) : "memory")

__device__ __forceinline__ void mma_tf32(float* c, const uint32_t* a,
                                         const uint32_t* b) {
    asm volatile(
        "mma.sync.aligned.m16n8k8.row.col.f32.tf32.tf32.f32 "
        "{%0,%1,%2,%3}, {%4,%5,%6,%7}, {%8,%9}, {%0,%1,%2,%3};"
        : "+f"(c[0]), "+f"(c[1]), "+f"(c[2]), "+f"(c[3])
        : "r"(a[0]), "r"(a[1]), "r"(a[2]), "r"(a[3]), "r"(b[0]), "r"(b[1]));
}

// ---------------- prep kernels ----------------
__global__ void round_tf32_kernel(const float4* __restrict__ in,
                                  float4* __restrict__ out, int n4) {
    int i = blockIdx.x * blockDim.x + threadIdx.x;
    if (i < n4) {
        float4 v = in[i];
        v.x = tf32r(v.x); v.y = tf32r(v.y); v.z = tf32r(v.z); v.w = tf32r(v.w);
        out[i] = v;
    }
}

// in [R,C] row-major -> out [C,R] row-major, tf32-rounded
__global__ void transpose_tf32_kernel(const float* __restrict__ in,
                                      float* __restrict__ out, int R, int C) {
    __shared__ float t[32][33];
    const int c0 = blockIdx.x * 32, r0 = blockIdx.y * 32;
    const int tx = threadIdx.x, ty = threadIdx.y;
    #pragma unroll
    for (int i = 0; i < 32; i += 8)
        t[ty + i][tx] = tf32r(in[(size_t)(r0 + ty + i) * C + c0 + tx]);
    __syncthreads();
    #pragma unroll
    for (int i = 0; i < 32; i += 8)
        out[(size_t)(c0 + ty + i) * R + r0 + tx] = t[tx][ty + i];
}

// ---------------- tf32 mma.sync GEMM ----------------
// C[M,N] = A[M,K] @ BT[N,K]^T (+bias).
// CTA 128x128, BK=32, 256 threads = 8 warps (2m x 4n), warp tile 64x32.
#define BM 128
#define BN 128
#define BK 32
#define LDK 36                              // 32 + 4 pad (keeps 16B align, no conflicts)
#define TILE_FLOATS (128 * LDK)             // per operand per stage
#define STAGE_FLOATS (2 * TILE_FLOATS)      // A + B
#define GEMM_SMEM (2 * STAGE_FLOATS * 4)    // 73728 bytes

__global__ void __launch_bounds__(256)
gemm_mma_kernel(const float* __restrict__ A, const float* __restrict__ BT,
                float* __restrict__ C, const float* __restrict__ bias,
                int M, int N, int K)
{
    extern __shared__ float smem[];

    const int tid = threadIdx.x;
    const int wid = tid >> 5, lid = tid & 31;
    const int wm = wid >> 2;            // 0..1  (64 rows each)
    const int wn = wid & 3;             // 0..3  (32 cols each)
    const int g = lid >> 2, t = lid & 3;
    const int m0 = blockIdx.y * BM, n0 = blockIdx.x * BN;

    const float* Ab = A + (size_t)m0 * K;
    const float* Bb = BT + (size_t)n0 * K;
    const int NC = K / BK;              // 32

    // loader: 256 threads, A tile = 128 rows x 8 float4 = 1024 -> 4/thread
    const uint32_t sbase = smem_u32(smem);
    auto load_chunk = [&](int c) {
        const int k0 = c * BK;
        const int s = c & 1;
        const uint32_t abase = sbase + s * STAGE_FLOATS * 4;
        const uint32_t bbase = abase + TILE_FLOATS * 4;
        #pragma unroll
        for (int i = 0; i < 4; i++) {
            int idx = tid + i * 256;
            int r = idx >> 3, c16 = idx & 7;
            uint32_t off = (uint32_t)(r * LDK + c16 * 4) * 4;
            cpa16(abase + off, Ab + (size_t)r * K + k0 + c16 * 4);
            cpa16(bbase + off, Bb + (size_t)r * K + k0 + c16 * 4);
        }
    };

    float acc[4][4][4];
    #pragma unroll
    for (int i = 0; i < 4; i++)
        #pragma unroll
        for (int j = 0; j < 4; j++)
            #pragma unroll
            for (int r = 0; r < 4; r++) acc[i][j][r] = 0.f;

    load_chunk(0); CP_COMMIT();
    load_chunk(1); CP_COMMIT();

    for (int c = 0; c < NC; c++) {
        CP_WAIT(1);
        __syncthreads();
        const float* As = smem + (c & 1) * STAGE_FLOATS;
        const float* Bs = As + TILE_FLOATS;

        // per-lane row base pointers
        const float* pa0[4]; const float* pa1[4]; const float* pb[4];
        #pragma unroll
        for (int mt = 0; mt < 4; mt++) {
            const int rb = wm * 64 + mt * 16;
            pa0[mt] = As + (rb + g) * LDK + t;
            pa1[mt] = As + (rb + g + 8) * LDK + t;
        }
        #pragma unroll
        for (int nt = 0; nt < 4; nt++)
            pb[nt] = Bs + (wn * 32 + nt * 8 + g) * LDK + t;

        #pragma unroll
        for (int ks = 0; ks < 4; ks++) {
            const int k0 = ks * 8;
            uint32_t af[4][4], bf[4][2];
            #pragma unroll
            for (int mt = 0; mt < 4; mt++) {
                af[mt][0] = __float_as_uint(pa0[mt][k0]);
                af[mt][1] = __float_as_uint(pa1[mt][k0]);
                af[mt][2] = __float_as_uint(pa0[mt][k0 + 4]);
                af[mt][3] = __float_as_uint(pa1[mt][k0 + 4]);
            }
            #pragma unroll
            for (int nt = 0; nt < 4; nt++) {
                bf[nt][0] = __float_as_uint(pb[nt][k0]);
                bf[nt][1] = __float_as_uint(pb[nt][k0 + 4]);
            }
            #pragma unroll
            for (int mt = 0; mt < 4; mt++)
                #pragma unroll
                for (int nt = 0; nt < 4; nt++)
                    mma_tf32(acc[mt][nt], af[mt], bf[nt]);
        }
        __syncthreads();
        if (c + 2 < NC) load_chunk(c + 2);
        CP_COMMIT();
    }

    // epilogue
    float* Cb = C + (size_t)m0 * N + n0;
    #pragma unroll
    for (int mt = 0; mt < 4; mt++) {
        const int r0 = wm * 64 + mt * 16 + g;
        #pragma unroll
        for (int nt = 0; nt < 4; nt++) {
            const int col = wn * 32 + nt * 8 + t * 2;
            float b0 = 0.f, b1 = 0.f;
            if (bias) { b0 = bias[n0 + col]; b1 = bias[n0 + col + 1]; }
            float2 v0 = make_float2(acc[mt][nt][0] + b0, acc[mt][nt][1] + b1);
            float2 v1 = make_float2(acc[mt][nt][2] + b0, acc[mt][nt][3] + b1);
            *(float2*)(Cb + (size_t)r0 * N + col) = v0;
            *(float2*)(Cb + (size_t)(r0 + 8) * N + col) = v1;
        }
    }
}

// ---------------------------------------------------------------------------
// Banded flash attention (fp32 SIMT; output rounded to tf32 for proj GEMM).
// ---------------------------------------------------------------------------
__global__ void __launch_bounds__(128) attn_kernel(
    const float* __restrict__ qkv, float* __restrict__ out)
{
    extern __shared__ float smemf[];
    float* Qs = smemf;
    float* Kt = Qs + 64 * PAD;
    float* Vs = Kt + 64 * PAD;
    float* Ss = Vs + 64 * PAD;

    const int tid = threadIdx.x;
    const int tx = tid & 7;
    const int ty = tid >> 3;
    const int n0 = blockIdx.x * 64;
    const int h  = blockIdx.y;
    const int b  = blockIdx.z;
    const float scale = 0.125f;

    const float* qbase = qkv + (size_t)b * SEQ * 3 * DM + h * HD;

    for (int idx = tid; idx < 64 * 16; idx += 128) {
        const int r  = idx >> 4;
        const int c4 = (idx & 15) * 4;
        float4 v = *(const float4*)(qbase + (size_t)(n0 + r) * 3 * DM + c4);
        v.x *= scale; v.y *= scale; v.z *= scale; v.w *= scale;
        *(float4*)&Qs[r * PAD + c4] = v;
    }

    float m[4], l[4], o[4][8];
    #pragma unroll
    for (int r = 0; r < 4; r++) {
        m[r] = -INFINITY; l[r] = 0.f;
        #pragma unroll
        for (int c = 0; c < 8; c++) o[r][c] = 0.f;
    }

    const int jlo = max(0, n0 - HALF);
    const int jhi = min(SEQ, n0 + 64 + HALF);

    for (int j0 = jlo; j0 < jhi; j0 += 64) {
        __syncthreads();
        for (int idx = tid; idx < 64 * 16; idx += 128) {
            const int r  = idx >> 4;
            const int c4 = (idx & 15) * 4;
            const float* rowp = qbase + (size_t)(j0 + r) * 3 * DM;
            float4 kv = *(const float4*)(rowp + DM + c4);
            Kt[(c4 + 0) * PAD + r] = kv.x;
            Kt[(c4 + 1) * PAD + r] = kv.y;
            Kt[(c4 + 2) * PAD + r] = kv.z;
            Kt[(c4 + 3) * PAD + r] = kv.w;
            float4 vv = *(const float4*)(rowp + 2 * DM + c4);
            *(float4*)&Vs[r * PAD + c4] = vv;
        }
        __syncthreads();

        float s[4][8];
        #pragma unroll
        for (int r = 0; r < 4; r++)
            #pragma unroll
            for (int c = 0; c < 8; c++) s[r][c] = 0.f;

        for (int d = 0; d < 64; d += 4) {
            float q[4][4];
            #pragma unroll
            for (int r = 0; r < 4; r++)
                *(float4*)q[r] = *(const float4*)&Qs[(ty * 4 + r) * PAD + d];
            #pragma unroll
            for (int dd = 0; dd < 4; dd++) {
                float kk[8];
                *(float4*)&kk[0] = *(const float4*)&Kt[(d + dd) * PAD + tx * 8];
                *(float4*)&kk[4] = *(const float4*)&Kt[(d + dd) * PAD + tx * 8 + 4];
                #pragma unroll
                for (int r = 0; r < 4; r++)
                    #pragma unroll
                    for (int c = 0; c < 8; c++)
                        s[r][c] += q[r][dd] * kk[c];
            }
        }

        #pragma unroll
        for (int r = 0; r < 4; r++) {
            const int i = n0 + ty * 4 + r;
            float mx = -INFINITY;
            #pragma unroll
            for (int c = 0; c < 8; c++) {
                const int j = j0 + tx * 8 + c;
                const bool ok = (j >= i - HALF) && (j <= i + HALF);
                s[r][c] = ok ? s[r][c] : -INFINITY;
                mx = fmaxf(mx, s[r][c]);
            }
            mx = fmaxf(mx, __shfl_xor_sync(0xffffffffu, mx, 1));
            mx = fmaxf(mx, __shfl_xor_sync(0xffffffffu, mx, 2));
            mx = fmaxf(mx, __shfl_xor_sync(0xffffffffu, mx, 4));
            const float newm = fmaxf(m[r], mx);
            const float corr = __expf(m[r] - newm);
            float sum = 0.f;
            #pragma unroll
            for (int c = 0; c < 8; c++) {
                const float p = (s[r][c] == -INFINITY) ? 0.f
                                                       : __expf(s[r][c] - newm);
                Ss[(ty * 4 + r) * PAD + tx * 8 + c] = p;
                sum += p;
            }
            sum += __shfl_xor_sync(0xffffffffu, sum, 1);
            sum += __shfl_xor_sync(0xffffffffu, sum, 2);
            sum += __shfl_xor_sync(0xffffffffu, sum, 4);
            l[r] = l[r] * corr + sum;
            m[r] = newm;
            #pragma unroll
            for (int c = 0; c < 8; c++) o[r][c] *= corr;
        }
        __syncthreads();

        for (int j = 0; j < 64; j += 4) {
            float p[4][4];
            #pragma unroll
            for (int r = 0; r < 4; r++)
                *(float4*)p[r] = *(const float4*)&Ss[(ty * 4 + r) * PAD + j];
            #pragma unroll
            for (int jj = 0; jj < 4; jj++) {
                float v8[8];
                *(float4*)&v8[0] = *(const float4*)&Vs[(j + jj) * PAD + tx * 8];
                *(float4*)&v8[4] = *(const float4*)&Vs[(j + jj) * PAD + tx * 8 + 4];
                #pragma unroll
                for (int r = 0; r < 4; r++)
                    #pragma unroll
                    for (int c = 0; c < 8; c++)
                        o[r][c] += p[r][jj] * v8[c];
            }
        }
    }

    #pragma unroll
    for (int r = 0; r < 4; r++) {
        const int i = n0 + ty * 4 + r;
        const float inv = 1.f / l[r];
        float* op = out + ((size_t)(b * SEQ + i)) * DM + h * HD + tx * 8;
        float4 v0 = make_float4(tf32r(o[r][0] * inv), tf32r(o[r][1] * inv),
                                tf32r(o[r][2] * inv), tf32r(o[r][3] * inv));
        float4 v1 = make_float4(tf32r(o[r][4] * inv), tf32r(o[r][5] * inv),
                                tf32r(o[r][6] * inv), tf32r(o[r][7] * inv));
        *(float4*)op = v0;
        *(float4*)(op + 4) = v1;
    }
}

// ---------------------------------------------------------------------------
extern "C" void kernel_launch(void* const* d_in, const int* in_sizes, int n_in,
                              void* d_out, int out_size)
{
    const float* x     = (const float*)d_in[0];  // [2,2048,1024]
    const float* Wqkv  = (const float*)d_in[1];  // [1024,3072]
    const float* Wproj = (const float*)d_in[2];  // [1024,1024]
    const float* bproj = (const float*)d_in[3];  // [1024]
    float* out = (float*)d_out;

    float *qkv, *attn, *xr, *wqkvT, *wprojT;
    cudaGetSymbolAddress((void**)&qkv, g_qkv);
    cudaGetSymbolAddress((void**)&attn, g_attn);
    cudaGetSymbolAddress((void**)&xr, g_xr);
    cudaGetSymbolAddress((void**)&wqkvT, g_wqkvT);
    cudaGetSymbolAddress((void**)&wprojT, g_wprojT);

    const int M = BATCH * SEQ;                    // 4096
    const size_t attn_smem = 4 * 64 * PAD * sizeof(float);
    cudaFuncSetAttribute(attn_kernel,
                         cudaFuncAttributeMaxDynamicSharedMemorySize,
                         (int)attn_smem);
    cudaFuncSetAttribute(gemm_mma_kernel,
                         cudaFuncAttributeMaxDynamicSharedMemorySize,
                         GEMM_SMEM);

    // 0) prep: round x to tf32; transpose+round weights
    {
        const int n4 = M * DM / 4;
        round_tf32_kernel<<<(n4 + 255) / 256, 256>>>(
            (const float4*)x, (float4*)xr, n4);
        dim3 tb(32, 8);
        transpose_tf32_kernel<<<dim3(3 * DM / 32, DM / 32), tb>>>(Wqkv, wqkvT, DM, 3 * DM);
        transpose_tf32_kernel<<<dim3(DM / 32, DM / 32), tb>>>(Wproj, wprojT, DM, DM);
    }
    // 1) QKV projection (tensor cores via mma.sync tf32)
    {
        dim3 grid(3 * DM / BN, M / BM);   // (24, 32)
        gemm_mma_kernel<<<grid, 256, GEMM_SMEM>>>(xr, wqkvT, qkv, nullptr,
                                                  M, 3 * DM, DM);
    }
    // 2) banded attention
    {
        dim3 grid(SEQ / 64, NH, BATCH);
        attn_kernel<<<grid, 128, attn_smem>>>(qkv, attn);
    }
    // 3) output projection + bias
    {
        dim3 grid(DM / BN, M / BM);       // (8, 32)
        gemm_mma_kernel<<<grid, 256, GEMM_SMEM>>>(attn, wprojT, out, bproj,
                                                  M, DM, DM);
    }
}

// round 4
// speedup vs baseline: 3.1961x; 1.7316x over previous
#include <cuda_runtime.h>
#include <math.h>
#include <stdint.h>

#define BATCH 2
#define SEQ   2048
#define DM    1024
#define NH    16
#define HD    64
#define HALF  256

// ---------------- scratch ----------------
__device__ float g_qkv[BATCH * SEQ * 3 * DM];   // [B,N,3,H,Dh] tf32-rounded
__device__ float g_attn[BATCH * SEQ * DM];      // [B,N,C] tf32-rounded
__device__ float g_xr[BATCH * SEQ * DM];        // x rounded to tf32
__device__ float g_wqkvT[3 * DM * DM];          // [3C,C] transposed+rounded
__device__ float g_wprojT[DM * DM];             // [C,C]  transposed+rounded

// ---------------- helpers ----------------
__device__ __forceinline__ float tf32r(float x) {
    uint32_t u; asm("cvt.rna.tf32.f32 %0, %1;" : "=r"(u) : "f"(x));
    return __uint_as_float(u);
}
__device__ __forceinline__ uint32_t smem_u32(const void* p) {
    uint32_t a;
    asm("{ .reg .u64 t; cvta.to.shared.u64 t, %1; cvt.u32.u64 %0, t; }"
        : "=r"(a) : "l"(p));
    return a;
}
__device__ __forceinline__ void cpa16(uint32_t dst, const void* src) {
    asm volatile("cp.async.cg.shared.global [%0], [%1], 16;"
                 :: "r"(dst), "l"(src));
}
#define CP_COMMIT() asm volatile("cp.async.commit_group;" ::: "memory")
#define CP_WAIT(n)  asm volatile("cp.async.wait_group %0;" :: "n"(n) : "memory")

__device__ __forceinline__ void mma_tf32(float* c, const uint32_t* a,
                                         const uint32_t* b) {
    asm volatile(
        "mma.sync.aligned.m16n8k8.row.col.f32.tf32.tf32.f32 "
        "{%0,%1,%2,%3}, {%4,%5,%6,%7}, {%8,%9}, {%0,%1,%2,%3};"
        : "+f"(c[0]), "+f"(c[1]), "+f"(c[2]), "+f"(c[3])
        : "r"(a[0]), "r"(a[1]), "r"(a[2]), "r"(a[3]), "r"(b[0]), "r"(b[1]));
}

// ---------------- prep kernels ----------------
__global__ void round_tf32_kernel(const float4* __restrict__ in,
                                  float4* __restrict__ out, int n4) {
    int i = blockIdx.x * blockDim.x + threadIdx.x;
    if (i < n4) {
        float4 v = in[i];
        v.x = tf32r(v.x); v.y = tf32r(v.y); v.z = tf32r(v.z); v.w = tf32r(v.w);
        out[i] = v;
    }
}

__global__ void transpose_tf32_kernel(const float* __restrict__ in,
                                      float* __restrict__ out, int R, int C) {
    __shared__ float t[32][33];
    const int c0 = blockIdx.x * 32, r0 = blockIdx.y * 32;
    const int tx = threadIdx.x, ty = threadIdx.y;
    #pragma unroll
    for (int i = 0; i < 32; i += 8)
        t[ty + i][tx] = tf32r(in[(size_t)(r0 + ty + i) * C + c0 + tx]);
    __syncthreads();
    #pragma unroll
    for (int i = 0; i < 32; i += 8)
        out[(size_t)(c0 + ty + i) * R + r0 + tx] = t[tx][ty + i];
}

// ---------------- tf32 mma.sync GEMM ----------------
#define BM 128
#define BN 128
#define BK 32
#define LDK 36
#define TILE_FLOATS (128 * LDK)
#define STAGE_FLOATS (2 * TILE_FLOATS)
#define GEMM_SMEM (2 * STAGE_FLOATS * 4)

__global__ void __launch_bounds__(256)
gemm_mma_kernel(const float* __restrict__ A, const float* __restrict__ BT,
                float* __restrict__ C, const float* __restrict__ bias,
                int M, int N, int K, int round_out)
{
    extern __shared__ float smem[];

    const int tid = threadIdx.x;
    const int wid = tid >> 5, lid = tid & 31;
    const int wm = wid >> 2;
    const int wn = wid & 3;
    const int g = lid >> 2, t = lid & 3;
    const int m0 = blockIdx.y * BM, n0 = blockIdx.x * BN;

    const float* Ab = A + (size_t)m0 * K;
    const float* Bb = BT + (size_t)n0 * K;
    const int NC = K / BK;

    const uint32_t sbase = smem_u32(smem);
    auto load_chunk = [&](int c) {
        const int k0 = c * BK;
        const int s = c & 1;
        const uint32_t abase = sbase + s * STAGE_FLOATS * 4;
        const uint32_t bbase = abase + TILE_FLOATS * 4;
        #pragma unroll
        for (int i = 0; i < 4; i++) {
            int idx = tid + i * 256;
            int r = idx >> 3, c16 = idx & 7;
            uint32_t off = (uint32_t)(r * LDK + c16 * 4) * 4;
            cpa16(abase + off, Ab + (size_t)r * K + k0 + c16 * 4);
            cpa16(bbase + off, Bb + (size_t)r * K + k0 + c16 * 4);
        }
    };

    float acc[4][4][4];
    #pragma unroll
    for (int i = 0; i < 4; i++)
        #pragma unroll
        for (int j = 0; j < 4; j++)
            #pragma unroll
            for (int r = 0; r < 4; r++) acc[i][j][r] = 0.f;

    load_chunk(0); CP_COMMIT();
    load_chunk(1); CP_COMMIT();

    for (int c = 0; c < NC; c++) {
        CP_WAIT(1);
        __syncthreads();
        const float* As = smem + (c & 1) * STAGE_FLOATS;
        const float* Bs = As + TILE_FLOATS;

        const float* pa0[4]; const float* pa1[4]; const float* pb[4];
        #pragma unroll
        for (int mt = 0; mt < 4; mt++) {
            const int rb = wm * 64 + mt * 16;
            pa0[mt] = As + (rb + g) * LDK + t;
            pa1[mt] = As + (rb + g + 8) * LDK + t;
        }
        #pragma unroll
        for (int nt = 0; nt < 4; nt++)
            pb[nt] = Bs + (wn * 32 + nt * 8 + g) * LDK + t;

        #pragma unroll
        for (int ks = 0; ks < 4; ks++) {
            const int k0 = ks * 8;
            uint32_t af[4][4], bf[4][2];
            #pragma unroll
            for (int mt = 0; mt < 4; mt++) {
                af[mt][0] = __float_as_uint(pa0[mt][k0]);
                af[mt][1] = __float_as_uint(pa1[mt][k0]);
                af[mt][2] = __float_as_uint(pa0[mt][k0 + 4]);
                af[mt][3] = __float_as_uint(pa1[mt][k0 + 4]);
            }
            #pragma unroll
            for (int nt = 0; nt < 4; nt++) {
                bf[nt][0] = __float_as_uint(pb[nt][k0]);
                bf[nt][1] = __float_as_uint(pb[nt][k0 + 4]);
            }
            #pragma unroll
            for (int mt = 0; mt < 4; mt++)
                #pragma unroll
                for (int nt = 0; nt < 4; nt++)
                    mma_tf32(acc[mt][nt], af[mt], bf[nt]);
        }
        __syncthreads();
        if (c + 2 < NC) load_chunk(c + 2);
        CP_COMMIT();
    }

    float* Cb = C + (size_t)m0 * N + n0;
    #pragma unroll
    for (int mt = 0; mt < 4; mt++) {
        const int r0 = wm * 64 + mt * 16 + g;
        #pragma unroll
        for (int nt = 0; nt < 4; nt++) {
            const int col = wn * 32 + nt * 8 + t * 2;
            float b0 = 0.f, b1 = 0.f;
            if (bias) { b0 = bias[n0 + col]; b1 = bias[n0 + col + 1]; }
            float2 v0 = make_float2(acc[mt][nt][0] + b0, acc[mt][nt][1] + b1);
            float2 v1 = make_float2(acc[mt][nt][2] + b0, acc[mt][nt][3] + b1);
            if (round_out) {
                v0.x = tf32r(v0.x); v0.y = tf32r(v0.y);
                v1.x = tf32r(v1.x); v1.y = tf32r(v1.y);
            }
            *(float2*)(Cb + (size_t)r0 * N + col) = v0;
            *(float2*)(Cb + (size_t)(r0 + 8) * N + col) = v1;
        }
    }
}

// ---------------------------------------------------------------------------
// Banded flash attention on mma.sync tf32.
// CTA = 64 queries x (head,batch); 4 warps; warp w owns rows 16w..16w+15.
// SMEM: Qs[64][68], Ks[2][64][68] (natural [j][d]), Vt[2][64][68] ([d][j]),
//       Ss[64][68] (P).
// ---------------------------------------------------------------------------
#define ALD 68
#define ATT_SMEM (6 * 64 * ALD * 4)     // 104448 bytes

__global__ void __launch_bounds__(128) attn_mma_kernel(
    const float* __restrict__ qkv, float* __restrict__ out)
{
    extern __shared__ float sm[];
    float* Qs = sm;                       // [64][68]
    float* Ks = Qs + 64 * ALD;            // [2][64][68]
    float* Vt = Ks + 2 * 64 * ALD;        // [2][64][68]
    float* Ss = Vt + 2 * 64 * ALD;        // [64][68]

    const int tid = threadIdx.x;
    const int w = tid >> 5, lane = tid & 31;
    const int g = lane >> 2, t = lane & 3;
    const int n0 = blockIdx.x * 64;
    const int h  = blockIdx.y;
    const int b  = blockIdx.z;
    const float scale = 0.125f;

    const float* base = qkv + (size_t)b * SEQ * 3 * DM + h * HD;

    const int jlo = max(0, n0 - HALF);
    const int jhi = min(SEQ, n0 + 64 + HALF);
    const int NT = (jhi - jlo) >> 6;

    const uint32_t sQ = smem_u32(Qs);
    const uint32_t sK = smem_u32(Ks);

    // prologue: Q + K0 via cp.async (one group)
    {
        #pragma unroll
        for (int i = 0; i < 8; i++) {
            int idx = tid + i * 128;
            int r = idx >> 4, c4 = (idx & 15) * 4;
            uint32_t off = (uint32_t)(r * ALD + c4) * 4;
            cpa16(sQ + off, base + (size_t)(n0 + r) * 3 * DM + c4);
            cpa16(sK + off, base + (size_t)(jlo + r) * 3 * DM + DM + c4);
        }
        CP_COMMIT();
    }

    // V staging registers: vr[jb][i] = V[jlo + jb*32 + lane][16w+4i .. +3]
    float4 vr[2][4];
    {
        const float* vb = base + 2 * DM + 16 * w;
        #pragma unroll
        for (int jb = 0; jb < 2; jb++)
            #pragma unroll
            for (int i = 0; i < 4; i++)
                vr[jb][i] = *(const float4*)(vb +
                    (size_t)(jlo + jb * 32 + lane) * 3 * DM + 4 * i);
    }

    float o[8][4];
    #pragma unroll
    for (int dt = 0; dt < 8; dt++)
        #pragma unroll
        for (int r = 0; r < 4; r++) o[dt][r] = 0.f;
    float m0 = -INFINITY, m1 = -INFINITY, l0 = 0.f, l1 = 0.f;

    const int rowA0 = (w * 16 + g) * ALD;
    const int rowA1 = rowA0 + 8 * ALD;
    const int i0 = n0 + w * 16 + g;
    const int i1 = i0 + 8;

    for (int c = 0; c < NT; c++) {
        const int j0 = jlo + c * 64;
        CP_WAIT(0);
        // store staged V transposed (conflict-free: lane -> j)
        {
            float* vbuf = Vt + (c & 1) * 64 * ALD;
            #pragma unroll
            for (int jb = 0; jb < 2; jb++)
                #pragma unroll
                for (int i = 0; i < 4; i++) {
                    const int d = 16 * w + 4 * i;
                    const int j = jb * 32 + lane;
                    vbuf[(d + 0) * ALD + j] = vr[jb][i].x;
                    vbuf[(d + 1) * ALD + j] = vr[jb][i].y;
                    vbuf[(d + 2) * ALD + j] = vr[jb][i].z;
                    vbuf[(d + 3) * ALD + j] = vr[jb][i].w;
                }
        }
        __syncthreads();

        if (c + 1 < NT) {
            // next K tile via cp.async
            const uint32_t kb = sK + (uint32_t)(((c + 1) & 1) * 64 * ALD * 4);
            #pragma unroll
            for (int i = 0; i < 8; i++) {
                int idx = tid + i * 128;
                int r = idx >> 4, c4 = (idx & 15) * 4;
                cpa16(kb + (uint32_t)(r * ALD + c4) * 4,
                      base + (size_t)(j0 + 64 + r) * 3 * DM + DM + c4);
            }
            CP_COMMIT();
            // next V tile into registers (LDG latency overlaps compute)
            const float* vb = base + 2 * DM + 16 * w;
            #pragma unroll
            for (int jb = 0; jb < 2; jb++)
                #pragma unroll
                for (int i = 0; i < 4; i++)
                    vr[jb][i] = *(const float4*)(vb +
                        (size_t)(j0 + 64 + jb * 32 + lane) * 3 * DM + 4 * i);
        }

        // ---- S = Q @ K^T ----
        float s[8][4];
        #pragma unroll
        for (int nt = 0; nt < 8; nt++)
            #pragma unroll
            for (int r = 0; r < 4; r++) s[nt][r] = 0.f;

        const float* kbuf = Ks + (c & 1) * 64 * ALD;
        #pragma unroll
        for (int ks = 0; ks < 8; ks++) {
            const int kk = ks * 8;
            uint32_t af[4];
            af[0] = __float_as_uint(Qs[rowA0 + kk + t]);
            af[1] = __float_as_uint(Qs[rowA1 + kk + t]);
            af[2] = __float_as_uint(Qs[rowA0 + kk + t + 4]);
            af[3] = __float_as_uint(Qs[rowA1 + kk + t + 4]);
            #pragma unroll
            for (int nt = 0; nt < 8; nt++) {
                uint32_t bf[2];
                const float* kp = kbuf + (8 * nt + g) * ALD + kk + t;
                bf[0] = __float_as_uint(kp[0]);
                bf[1] = __float_as_uint(kp[4]);
                mma_tf32(s[nt], af, bf);
            }
        }

        // ---- scale + mask + online softmax (accumulator layout) ----
        const bool masked = (j0 - n0 == HALF) || (n0 - j0 == HALF);
        #pragma unroll
        for (int nt = 0; nt < 8; nt++) {
            #pragma unroll
            for (int r = 0; r < 4; r++) s[nt][r] *= scale;
            if (masked) {
                const int jc = j0 + 8 * nt + 2 * t;
                if (abs(i0 - jc) > HALF)       s[nt][0] = -INFINITY;
                if (abs(i0 - (jc + 1)) > HALF) s[nt][1] = -INFINITY;
                if (abs(i1 - jc) > HALF)       s[nt][2] = -INFINITY;
                if (abs(i1 - (jc + 1)) > HALF) s[nt][3] = -INFINITY;
            }
        }
        float mx0 = -INFINITY, mx1 = -INFINITY;
        #pragma unroll
        for (int nt = 0; nt < 8; nt++) {
            mx0 = fmaxf(mx0, fmaxf(s[nt][0], s[nt][1]));
            mx1 = fmaxf(mx1, fmaxf(s[nt][2], s[nt][3]));
        }
        mx0 = fmaxf(mx0, __shfl_xor_sync(0xffffffffu, mx0, 1));
        mx0 = fmaxf(mx0, __shfl_xor_sync(0xffffffffu, mx0, 2));
        mx1 = fmaxf(mx1, __shfl_xor_sync(0xffffffffu, mx1, 1));
        mx1 = fmaxf(mx1, __shfl_xor_sync(0xffffffffu, mx1, 2));
        const float nm0 = fmaxf(m0, mx0), nm1 = fmaxf(m1, mx1);
        const float corr0 = __expf(m0 - nm0), corr1 = __expf(m1 - nm1);
        m0 = nm0; m1 = nm1;

        float sum0 = 0.f, sum1 = 0.f;
        #pragma unroll
        for (int nt = 0; nt < 8; nt++) {
            s[nt][0] = __expf(s[nt][0] - nm0);
            s[nt][1] = __expf(s[nt][1] - nm0);
            s[nt][2] = __expf(s[nt][2] - nm1);
            s[nt][3] = __expf(s[nt][3] - nm1);
            sum0 += s[nt][0] + s[nt][1];
            sum1 += s[nt][2] + s[nt][3];
            // store P (float2 per row-half)
            float* sp = Ss + rowA0 + 8 * nt + 2 * t;
            *(float2*)sp = make_float2(s[nt][0], s[nt][1]);
            *(float2*)(sp + 8 * ALD) = make_float2(s[nt][2], s[nt][3]);
        }
        sum0 += __shfl_xor_sync(0xffffffffu, sum0, 1);
        sum0 += __shfl_xor_sync(0xffffffffu, sum0, 2);
        sum1 += __shfl_xor_sync(0xffffffffu, sum1, 1);
        sum1 += __shfl_xor_sync(0xffffffffu, sum1, 2);
        l0 = l0 * corr0 + sum0;
        l1 = l1 * corr1 + sum1;
        #pragma unroll
        for (int dt = 0; dt < 8; dt++) {
            o[dt][0] *= corr0; o[dt][1] *= corr0;
            o[dt][2] *= corr1; o[dt][3] *= corr1;
        }
        __syncwarp();

        // ---- O += P @ V ----
        const float* vbuf = Vt + (c & 1) * 64 * ALD;
        #pragma unroll
        for (int ks = 0; ks < 8; ks++) {
            const int kk = ks * 8;
            uint32_t af[4];
            af[0] = __float_as_uint(Ss[rowA0 + kk + t]);
            af[1] = __float_as_uint(Ss[rowA1 + kk + t]);
            af[2] = __float_as_uint(Ss[rowA0 + kk + t + 4]);
            af[3] = __float_as_uint(Ss[rowA1 + kk + t + 4]);
            #pragma unroll
            for (int dt = 0; dt < 8; dt++) {
                uint32_t bf[2];
                const float* vp = vbuf + (8 * dt + g) * ALD + kk + t;
                bf[0] = __float_as_uint(vp[0]);
                bf[1] = __float_as_uint(vp[4]);
                mma_tf32(o[dt], af, bf);
            }
        }
    }

    // epilogue: normalize + tf32-round + store
    const float inv0 = 1.f / l0, inv1 = 1.f / l1;
    float* o0 = out + ((size_t)(b * SEQ + i0)) * DM + h * HD;
    float* o1 = o0 + (size_t)8 * DM;
    #pragma unroll
    for (int dt = 0; dt < 8; dt++) {
        const int col = 8 * dt + 2 * t;
        *(float2*)(o0 + col) = make_float2(tf32r(o[dt][0] * inv0),
                                           tf32r(o[dt][1] * inv0));
        *(float2*)(o1 + col) = make_float2(tf32r(o[dt][2] * inv1),
                                           tf32r(o[dt][3] * inv1));
    }
}

// ---------------------------------------------------------------------------
extern "C" void kernel_launch(void* const* d_in, const int* in_sizes, int n_in,
                              void* d_out, int out_size)
{
    const float* x     = (const float*)d_in[0];
    const float* Wqkv  = (const float*)d_in[1];
    const float* Wproj = (const float*)d_in[2];
    const float* bproj = (const float*)d_in[3];
    float* out = (float*)d_out;

    float *qkv, *attn, *xr, *wqkvT, *wprojT;
    cudaGetSymbolAddress((void**)&qkv, g_qkv);
    cudaGetSymbolAddress((void**)&attn, g_attn);
    cudaGetSymbolAddress((void**)&xr, g_xr);
    cudaGetSymbolAddress((void**)&wqkvT, g_wqkvT);
    cudaGetSymbolAddress((void**)&wprojT, g_wprojT);

    const int M = BATCH * SEQ;
    cudaFuncSetAttribute(attn_mma_kernel,
                         cudaFuncAttributeMaxDynamicSharedMemorySize,
                         ATT_SMEM);
    cudaFuncSetAttribute(gemm_mma_kernel,
                         cudaFuncAttributeMaxDynamicSharedMemorySize,
                         GEMM_SMEM);

    // 0) prep
    {
        const int n4 = M * DM / 4;
        round_tf32_kernel<<<(n4 + 255) / 256, 256>>>(
            (const float4*)x, (float4*)xr, n4);
        dim3 tb(32, 8);
        transpose_tf32_kernel<<<dim3(3 * DM / 32, DM / 32), tb>>>(Wqkv, wqkvT, DM, 3 * DM);
        transpose_tf32_kernel<<<dim3(DM / 32, DM / 32), tb>>>(Wproj, wprojT, DM, DM);
    }
    // 1) QKV projection (outputs tf32-rounded for attention MMA)
    {
        dim3 grid(3 * DM / BN, M / BM);
        gemm_mma_kernel<<<grid, 256, GEMM_SMEM>>>(xr, wqkvT, qkv, nullptr,
                                                  M, 3 * DM, DM, 1);
    }
    // 2) banded attention (tensor cores)
    {
        dim3 grid(SEQ / 64, NH, BATCH);
        attn_mma_kernel<<<grid, 128, ATT_SMEM>>>(qkv, attn);
    }
    // 3) output projection + bias
    {
        dim3 grid(DM / BN, M / BM);
        gemm_mma_kernel<<<grid, 256, GEMM_SMEM>>>(attn, wprojT, out, bproj,
                                                  M, DM, DM, 0);
    }
}

// round 5
// speedup vs baseline: 3.3613x; 1.0517x over previous
#include <cuda_runtime.h>
#include <math.h>
#include <stdint.h>

#define BATCH 2
#define SEQ   2048
#define DM    1024
#define NH    16
#define HD    64
#define HALF  256

// ---------------- scratch ----------------
__device__ float g_qkv[BATCH * SEQ * 3 * DM];   // [B,N,3,H,Dh] natural, tf32
__device__ float g_attn[BATCH * SEQ * DM];      // [B,N,C] K-PERMUTED, tf32
__device__ float g_xr[BATCH * SEQ * DM];        // x K-PERMUTED, tf32
__device__ float g_wqkvT[3 * DM * DM];          // [3C,C] transposed, K-PERM
__device__ float g_wprojT[DM * DM];             // [C,C]  transposed, K-PERM

// ---------------- helpers ----------------
__device__ __forceinline__ float tf32r(float x) {
    uint32_t u; asm("cvt.rna.tf32.f32 %0, %1;" : "=r"(u) : "f"(x));
    return __uint_as_float(u);
}
__device__ __forceinline__ uint32_t smem_u32(const void* p) {
    uint32_t a;
    asm("{ .reg .u64 t; cvta.to.shared.u64 t, %1; cvt.u32.u64 %0, t; }"
        : "=r"(a) : "l"(p));
    return a;
}
__device__ __forceinline__ void cpa16(uint32_t dst, const void* src) {
    asm volatile("cp.async.cg.shared.global [%0], [%1], 16;"
                 :: "r"(dst), "l"(src));
}
#define CP_COMMIT() asm volatile("cp.async.commit_group;" ::: "memory")
#define CP_WAIT(n)  asm volatile("cp.async.wait_group %0;" :: "n"(n) : "memory")

__device__ __forceinline__ void mma_tf32(float* c, const uint32_t* a,
                                         const uint32_t* b) {
    asm volatile(
        "mma.sync.aligned.m16n8k8.row.col.f32.tf32.tf32.f32 "
        "{%0,%1,%2,%3}, {%4,%5,%6,%7}, {%8,%9}, {%0,%1,%2,%3};"
        : "+f"(c[0]), "+f"(c[1]), "+f"(c[2]), "+f"(c[3])
        : "r"(a[0]), "r"(a[1]), "r"(a[2]), "r"(a[3]), "r"(b[0]), "r"(b[1]));
}

// ---------------- prep kernels (K-permuted writers) ----------------
// natural group [k0..k7] -> stored [k0,k4,k1,k5, k2,k6,k3,k7]
__global__ void round_perm_tf32_kernel(const float4* __restrict__ in,
                                       float4* __restrict__ out, int n8) {
    int i = blockIdx.x * blockDim.x + threadIdx.x;
    if (i < n8) {
        float4 lo = in[2 * i], hi = in[2 * i + 1];
        float4 o0 = make_float4(tf32r(lo.x), tf32r(hi.x),
                                tf32r(lo.y), tf32r(hi.y));
        float4 o1 = make_float4(tf32r(lo.z), tf32r(hi.z),
                                tf32r(lo.w), tf32r(hi.w));
        out[2 * i] = o0; out[2 * i + 1] = o1;
    }
}

// in [R,C] -> out [C,R], out-col (the K dim) permuted within 8-groups
__global__ void transpose_perm_tf32_kernel(const float* __restrict__ in,
                                           float* __restrict__ out,
                                           int R, int C) {
    __shared__ float t[32][33];
    const int c0 = blockIdx.x * 32, r0 = blockIdx.y * 32;
    const int tx = threadIdx.x, ty = threadIdx.y;
    #pragma unroll
    for (int i = 0; i < 32; i += 8)
        t[ty + i][tx] = tf32r(in[(size_t)(r0 + ty + i) * C + c0 + tx]);
    __syncthreads();
    const int k7 = tx & 7;
    const int pp = (tx & ~7) | ((k7 < 4) ? (2 * k7) : (2 * (k7 - 4) + 1));
    #pragma unroll
    for (int i = 0; i < 32; i += 8)
        out[(size_t)(c0 + ty + i) * R + r0 + pp] = t[tx][ty + i];
}

// ---------------- tf32 mma.sync GEMM, 128x256 CTA, LDS.64 fragments ------
#define BM 128
#define BN 256
#define BK 32
#define LDK 40
#define A_FLOATS (BM * LDK)                 // 5120
#define B_FLOATS (BN * LDK)                 // 10240
#define STAGE_FLOATS (A_FLOATS + B_FLOATS)  // 15360
#define GSTAGES 3
#define GEMM_SMEM (GSTAGES * STAGE_FLOATS * 4)   // 184320

__global__ void __launch_bounds__(256, 1)
gemm_mma_kernel(const float* __restrict__ A, const float* __restrict__ BT,
                float* __restrict__ C, const float* __restrict__ bias,
                int M, int N, int K, int round_out)
{
    extern __shared__ float smem[];

    const int tid = threadIdx.x;
    const int wid = tid >> 5, lid = tid & 31;
    const int wm = wid >> 2;            // 0..1  (64 rows)
    const int wn = wid & 3;             // 0..3  (64 cols)
    const int g = lid >> 2, t = lid & 3;
    const int m0 = blockIdx.y * BM, n0 = blockIdx.x * BN;

    const float* Ab = A + (size_t)m0 * K;
    const float* Bb = BT + (size_t)n0 * K;
    const int NC = K / BK;              // 32

    const uint32_t sbase = smem_u32(smem);
    auto load_chunk = [&](int c) {
        const int k0 = c * BK;
        const uint32_t st = sbase + (uint32_t)((c % GSTAGES) * STAGE_FLOATS * 4);
        const uint32_t bbase = st + A_FLOATS * 4;
        #pragma unroll
        for (int i = 0; i < 4; i++) {       // A: 128 rows x 8 chunks
            int idx = tid + i * 256;
            int r = idx >> 3, c16 = idx & 7;
            cpa16(st + (uint32_t)(r * 160 + c16 * 16),
                  Ab + (size_t)r * K + k0 + c16 * 4);
        }
        #pragma unroll
        for (int i = 0; i < 8; i++) {       // B: 256 rows x 8 chunks
            int idx = tid + i * 256;
            int r = idx >> 3, c16 = idx & 7;
            cpa16(bbase + (uint32_t)(r * 160 + c16 * 16),
                  Bb + (size_t)r * K + k0 + c16 * 4);
        }
    };

    float acc[4][8][4];
    #pragma unroll
    for (int i = 0; i < 4; i++)
        #pragma unroll
        for (int j = 0; j < 8; j++)
            #pragma unroll
            for (int r = 0; r < 4; r++) acc[i][j][r] = 0.f;

    load_chunk(0); CP_COMMIT();
    load_chunk(1); CP_COMMIT();

    for (int c = 0; c < NC; c++) {
        CP_WAIT(1);
        __syncthreads();
        if (c + 2 < NC) load_chunk(c + 2);
        CP_COMMIT();

        const float* As = smem + (c % GSTAGES) * STAGE_FLOATS;
        const float* Bs = As + A_FLOATS;

        #pragma unroll
        for (int ks = 0; ks < 4; ks++) {
            const int ko = ks * 8 + 2 * t;
            float2 av[4][2];
            #pragma unroll
            for (int mt = 0; mt < 4; mt++) {
                const int rb = (wm * 64 + mt * 16 + g) * LDK;
                av[mt][0] = *(const float2*)&As[rb + ko];
                av[mt][1] = *(const float2*)&As[rb + 8 * LDK + ko];
            }
            float2 bv[8];
            #pragma unroll
            for (int nt = 0; nt < 8; nt++)
                bv[nt] = *(const float2*)&Bs[(wn * 64 + nt * 8 + g) * LDK + ko];

            #pragma unroll
            for (int mt = 0; mt < 4; mt++) {
                uint32_t af[4];
                af[0] = __float_as_uint(av[mt][0].x);
                af[1] = __float_as_uint(av[mt][1].x);
                af[2] = __float_as_uint(av[mt][0].y);
                af[3] = __float_as_uint(av[mt][1].y);
                #pragma unroll
                for (int nt = 0; nt < 8; nt++) {
                    uint32_t bf[2];
                    bf[0] = __float_as_uint(bv[nt].x);
                    bf[1] = __float_as_uint(bv[nt].y);
                    mma_tf32(acc[mt][nt], af, bf);
                }
            }
        }
    }

    // epilogue (natural N columns)
    float* Cb = C + (size_t)m0 * N + n0;
    #pragma unroll
    for (int mt = 0; mt < 4; mt++) {
        const int r0 = wm * 64 + mt * 16 + g;
        #pragma unroll
        for (int nt = 0; nt < 8; nt++) {
            const int col = wn * 64 + nt * 8 + t * 2;
            float b0 = 0.f, b1 = 0.f;
            if (bias) { b0 = bias[n0 + col]; b1 = bias[n0 + col + 1]; }
            float2 v0 = make_float2(acc[mt][nt][0] + b0, acc[mt][nt][1] + b1);
            float2 v1 = make_float2(acc[mt][nt][2] + b0, acc[mt][nt][3] + b1);
            if (round_out) {
                v0.x = tf32r(v0.x); v0.y = tf32r(v0.y);
                v1.x = tf32r(v1.x); v1.y = tf32r(v1.y);
            }
            *(float2*)(Cb + (size_t)r0 * N + col) = v0;
            *(float2*)(Cb + (size_t)(r0 + 8) * N + col) = v1;
        }
    }
}

// ---------------------------------------------------------------------------
// Banded flash attention on mma.sync tf32 (unchanged except permuted output).
// ---------------------------------------------------------------------------
#define ALD 68
#define ATT_SMEM (6 * 64 * ALD * 4)

__global__ void __launch_bounds__(128) attn_mma_kernel(
    const float* __restrict__ qkv, float* __restrict__ out)
{
    extern __shared__ float sm[];
    float* Qs = sm;
    float* Ks = Qs + 64 * ALD;
    float* Vt = Ks + 2 * 64 * ALD;
    float* Ss = Vt + 2 * 64 * ALD;

    const int tid = threadIdx.x;
    const int w = tid >> 5, lane = tid & 31;
    const int g = lane >> 2, t = lane & 3;
    const int n0 = blockIdx.x * 64;
    const int h  = blockIdx.y;
    const int b  = blockIdx.z;
    const float scale = 0.125f;

    const float* base = qkv + (size_t)b * SEQ * 3 * DM + h * HD;

    const int jlo = max(0, n0 - HALF);
    const int jhi = min(SEQ, n0 + 64 + HALF);
    const int NT = (jhi - jlo) >> 6;

    const uint32_t sQ = smem_u32(Qs);
    const uint32_t sK = smem_u32(Ks);

    {
        #pragma unroll
        for (int i = 0; i < 8; i++) {
            int idx = tid + i * 128;
            int r = idx >> 4, c4 = (idx & 15) * 4;
            uint32_t off = (uint32_t)(r * ALD + c4) * 4;
            cpa16(sQ + off, base + (size_t)(n0 + r) * 3 * DM + c4);
            cpa16(sK + off, base + (size_t)(jlo + r) * 3 * DM + DM + c4);
        }
        CP_COMMIT();
    }

    float4 vr[2][4];
    {
        const float* vb = base + 2 * DM + 16 * w;
        #pragma unroll
        for (int jb = 0; jb < 2; jb++)
            #pragma unroll
            for (int i = 0; i < 4; i++)
                vr[jb][i] = *(const float4*)(vb +
                    (size_t)(jlo + jb * 32 + lane) * 3 * DM + 4 * i);
    }

    float o[8][4];
    #pragma unroll
    for (int dt = 0; dt < 8; dt++)
        #pragma unroll
        for (int r = 0; r < 4; r++) o[dt][r] = 0.f;
    float m0 = -INFINITY, m1 = -INFINITY, l0 = 0.f, l1 = 0.f;

    const int rowA0 = (w * 16 + g) * ALD;
    const int rowA1 = rowA0 + 8 * ALD;
    const int i0 = n0 + w * 16 + g;
    const int i1 = i0 + 8;

    for (int c = 0; c < NT; c++) {
        const int j0 = jlo + c * 64;
        CP_WAIT(0);
        {
            float* vbuf = Vt + (c & 1) * 64 * ALD;
            #pragma unroll
            for (int jb = 0; jb < 2; jb++)
                #pragma unroll
                for (int i = 0; i < 4; i++) {
                    const int d = 16 * w + 4 * i;
                    const int j = jb * 32 + lane;
                    vbuf[(d + 0) * ALD + j] = vr[jb][i].x;
                    vbuf[(d + 1) * ALD + j] = vr[jb][i].y;
                    vbuf[(d + 2) * ALD + j] = vr[jb][i].z;
                    vbuf[(d + 3) * ALD + j] = vr[jb][i].w;
                }
        }
        __syncthreads();

        if (c + 1 < NT) {
            const uint32_t kb = sK + (uint32_t)(((c + 1) & 1) * 64 * ALD * 4);
            #pragma unroll
            for (int i = 0; i < 8; i++) {
                int idx = tid + i * 128;
                int r = idx >> 4, c4 = (idx & 15) * 4;
                cpa16(kb + (uint32_t)(r * ALD + c4) * 4,
                      base + (size_t)(j0 + 64 + r) * 3 * DM + DM + c4);
            }
            CP_COMMIT();
            const float* vb = base + 2 * DM + 16 * w;
            #pragma unroll
            for (int jb = 0; jb < 2; jb++)
                #pragma unroll
                for (int i = 0; i < 4; i++)
                    vr[jb][i] = *(const float4*)(vb +
                        (size_t)(j0 + 64 + jb * 32 + lane) * 3 * DM + 4 * i);
        }

        float s[8][4];
        #pragma unroll
        for (int nt = 0; nt < 8; nt++)
            #pragma unroll
            for (int r = 0; r < 4; r++) s[nt][r] = 0.f;

        const float* kbuf = Ks + (c & 1) * 64 * ALD;
        #pragma unroll
        for (int ks = 0; ks < 8; ks++) {
            const int kk = ks * 8;
            uint32_t af[4];
            af[0] = __float_as_uint(Qs[rowA0 + kk + t]);
            af[1] = __float_as_uint(Qs[rowA1 + kk + t]);
            af[2] = __float_as_uint(Qs[rowA0 + kk + t + 4]);
            af[3] = __float_as_uint(Qs[rowA1 + kk + t + 4]);
            #pragma unroll
            for (int nt = 0; nt < 8; nt++) {
                uint32_t bf[2];
                const float* kp = kbuf + (8 * nt + g) * ALD + kk + t;
                bf[0] = __float_as_uint(kp[0]);
                bf[1] = __float_as_uint(kp[4]);
                mma_tf32(s[nt], af, bf);
            }
        }

        const bool masked = (j0 - n0 == HALF) || (n0 - j0 == HALF);
        #pragma unroll
        for (int nt = 0; nt < 8; nt++) {
            #pragma unroll
            for (int r = 0; r < 4; r++) s[nt][r] *= scale;
            if (masked) {
                const int jc = j0 + 8 * nt + 2 * t;
                if (abs(i0 - jc) > HALF)       s[nt][0] = -INFINITY;
                if (abs(i0 - (jc + 1)) > HALF) s[nt][1] = -INFINITY;
                if (abs(i1 - jc) > HALF)       s[nt][2] = -INFINITY;
                if (abs(i1 - (jc + 1)) > HALF) s[nt][3] = -INFINITY;
            }
        }
        float mx0 = -INFINITY, mx1 = -INFINITY;
        #pragma unroll
        for (int nt = 0; nt < 8; nt++) {
            mx0 = fmaxf(mx0, fmaxf(s[nt][0], s[nt][1]));
            mx1 = fmaxf(mx1, fmaxf(s[nt][2], s[nt][3]));
        }
        mx0 = fmaxf(mx0, __shfl_xor_sync(0xffffffffu, mx0, 1));
        mx0 = fmaxf(mx0, __shfl_xor_sync(0xffffffffu, mx0, 2));
        mx1 = fmaxf(mx1, __shfl_xor_sync(0xffffffffu, mx1, 1));
        mx1 = fmaxf(mx1, __shfl_xor_sync(0xffffffffu, mx1, 2));
        const float nm0 = fmaxf(m0, mx0), nm1 = fmaxf(m1, mx1);
        const float corr0 = __expf(m0 - nm0), corr1 = __expf(m1 - nm1);
        m0 = nm0; m1 = nm1;

        float sum0 = 0.f, sum1 = 0.f;
        #pragma unroll
        for (int nt = 0; nt < 8; nt++) {
            s[nt][0] = __expf(s[nt][0] - nm0);
            s[nt][1] = __expf(s[nt][1] - nm0);
            s[nt][2] = __expf(s[nt][2] - nm1);
            s[nt][3] = __expf(s[nt][3] - nm1);
            sum0 += s[nt][0] + s[nt][1];
            sum1 += s[nt][2] + s[nt][3];
            float* sp = Ss + rowA0 + 8 * nt + 2 * t;
            *(float2*)sp = make_float2(s[nt][0], s[nt][1]);
            *(float2*)(sp + 8 * ALD) = make_float2(s[nt][2], s[nt][3]);
        }
        sum0 += __shfl_xor_sync(0xffffffffu, sum0, 1);
        sum0 += __shfl_xor_sync(0xffffffffu, sum0, 2);
        sum1 += __shfl_xor_sync(0xffffffffu, sum1, 1);
        sum1 += __shfl_xor_sync(0xffffffffu, sum1, 2);
        l0 = l0 * corr0 + sum0;
        l1 = l1 * corr1 + sum1;
        #pragma unroll
        for (int dt = 0; dt < 8; dt++) {
            o[dt][0] *= corr0; o[dt][1] *= corr0;
            o[dt][2] *= corr1; o[dt][3] *= corr1;
        }
        __syncwarp();

        const float* vbuf = Vt + (c & 1) * 64 * ALD;
        #pragma unroll
        for (int ks = 0; ks < 8; ks++) {
            const int kk = ks * 8;
            uint32_t af[4];
            af[0] = __float_as_uint(Ss[rowA0 + kk + t]);
            af[1] = __float_as_uint(Ss[rowA1 + kk + t]);
            af[2] = __float_as_uint(Ss[rowA0 + kk + t + 4]);
            af[3] = __float_as_uint(Ss[rowA1 + kk + t + 4]);
            #pragma unroll
            for (int dt = 0; dt < 8; dt++) {
                uint32_t bf[2];
                const float* vp = vbuf + (8 * dt + g) * ALD + kk + t;
                bf[0] = __float_as_uint(vp[0]);
                bf[1] = __float_as_uint(vp[4]);
                mma_tf32(o[dt], af, bf);
            }
        }
    }

    // epilogue: normalize + tf32 + K-PERMUTED store (within 8-col groups)
    const float inv0 = 1.f / l0, inv1 = 1.f / l1;
    float* o0 = out + ((size_t)(b * SEQ + i0)) * DM + h * HD;
    float* o1 = o0 + (size_t)8 * DM;
    const int p0 = (t < 2) ? (4 * t) : (4 * t - 7);   // pos of natural 2t
    #pragma unroll
    for (int dt = 0; dt < 8; dt++) {
        const int cb = 8 * dt;
        o0[cb + p0]     = tf32r(o[dt][0] * inv0);
        o0[cb + p0 + 2] = tf32r(o[dt][1] * inv0);
        o1[cb + p0]     = tf32r(o[dt][2] * inv1);
        o1[cb + p0 + 2] = tf32r(o[dt][3] * inv1);
    }
}

// ---------------------------------------------------------------------------
extern "C" void kernel_launch(void* const* d_in, const int* in_sizes, int n_in,
                              void* d_out, int out_size)
{
    const float* x     = (const float*)d_in[0];
    const float* Wqkv  = (const float*)d_in[1];
    const float* Wproj = (const float*)d_in[2];
    const float* bproj = (const float*)d_in[3];
    float* out = (float*)d_out;

    float *qkv, *attn, *xr, *wqkvT, *wprojT;
    cudaGetSymbolAddress((void**)&qkv, g_qkv);
    cudaGetSymbolAddress((void**)&attn, g_attn);
    cudaGetSymbolAddress((void**)&xr, g_xr);
    cudaGetSymbolAddress((void**)&wqkvT, g_wqkvT);
    cudaGetSymbolAddress((void**)&wprojT, g_wprojT);

    const int M = BATCH * SEQ;
    cudaFuncSetAttribute(attn_mma_kernel,
                         cudaFuncAttributeMaxDynamicSharedMemorySize,
                         ATT_SMEM);
    cudaFuncSetAttribute(gemm_mma_kernel,
                         cudaFuncAttributeMaxDynamicSharedMemorySize,
                         GEMM_SMEM);

    // 0) prep (all GEMM operands stored K-permuted)
    {
        const int n8 = M * DM / 8;
        round_perm_tf32_kernel<<<(n8 + 255) / 256, 256>>>(
            (const float4*)x, (float4*)xr, n8);
        dim3 tb(32, 8);
        transpose_perm_tf32_kernel<<<dim3(3 * DM / 32, DM / 32), tb>>>(
            Wqkv, wqkvT, DM, 3 * DM);
        transpose_perm_tf32_kernel<<<dim3(DM / 32, DM / 32), tb>>>(
            Wproj, wprojT, DM, DM);
    }
    // 1) QKV projection (natural output, tf32-rounded for attention)
    {
        dim3 grid(3 * DM / BN, M / BM);   // (12, 32)
        gemm_mma_kernel<<<grid, 256, GEMM_SMEM>>>(xr, wqkvT, qkv, nullptr,
                                                  M, 3 * DM, DM, 1);
    }
    // 2) banded attention (permuted output feeds proj GEMM)
    {
        dim3 grid(SEQ / 64, NH, BATCH);
        attn_mma_kernel<<<grid, 128, ATT_SMEM>>>(qkv, attn);
    }
    // 3) output projection + bias (natural output)
    {
        dim3 grid(DM / BN, M / BM);       // (4, 32)
        gemm_mma_kernel<<<grid, 256, GEMM_SMEM>>>(attn, wprojT, out, bproj,
                                                  M, DM, DM, 0);
    }
}